// round 2
// baseline (speedup 1.0000x reference)
#include <cuda_runtime.h>

#define NN 100000
#define NE 800000
#define HIDD 64
#define EMBD 128
#define NGR 64
#define SCAN_B 512
#define NBLK ((NN + SCAN_B - 1) / SCAN_B)   // 196
#define FEAT_SZ (NN * HIDD)

// ---------------- scratch (device globals; no allocation allowed) ----------
__device__ int   g_cnt[NN];          // in-degree
__device__ int   g_rowstart[NN];     // CSR row start (by dst)
__device__ int   g_cursor[NN];       // fill cursors
__device__ int   g_col[NE];          // src node per incoming edge
__device__ float g_dn[NN];           // deg^-1/2 (clamped)
__device__ int   g_bsum[SCAN_B];     // scan partials
// feature slots: 0 = layer input, 1..3 = hop buffers, 4/5 = layer out ping-pong
__device__ float g_feat[6 * FEAT_SZ];
__device__ float g_gsum[NGR * HIDD];
__device__ int   g_gcnt[NGR];

__device__ __forceinline__ float* FEAT(int s) { return g_feat + (size_t)s * FEAT_SZ; }

// ---------------- copy input h into slot 0 ----------------------------------
__global__ void k_copyin(const float* __restrict__ h) {
    int i = blockIdx.x * blockDim.x + threadIdx.x;   // float4 index
    if (i < FEAT_SZ / 4)
        ((float4*)g_feat)[i] = ((const float4*)h)[i];
}

// ---------------- graph preprocessing --------------------------------------
__global__ void k_zero() {
    int i = blockIdx.x * blockDim.x + threadIdx.x;
    if (i < NN) g_cnt[i] = 0;
    if (i < NGR * HIDD) g_gsum[i] = 0.f;
    if (i < NGR) g_gcnt[i] = 0;
}

__global__ void k_count(const int* __restrict__ dst) {
    int i = blockIdx.x * blockDim.x + threadIdx.x;
    if (i < NE) atomicAdd(&g_cnt[dst[i]], 1);
}

__global__ void k_scanA() {
    __shared__ int s[SCAN_B];
    int i = blockIdx.x * SCAN_B + threadIdx.x;
    int v = (i < NN) ? g_cnt[i] : 0;
    s[threadIdx.x] = v;
    __syncthreads();
    for (int off = 1; off < SCAN_B; off <<= 1) {
        int t = (threadIdx.x >= off) ? s[threadIdx.x - off] : 0;
        __syncthreads();
        s[threadIdx.x] += t;
        __syncthreads();
    }
    if (i < NN) g_rowstart[i] = s[threadIdx.x] - v;  // exclusive within block
    if (threadIdx.x == SCAN_B - 1) g_bsum[blockIdx.x] = s[SCAN_B - 1];
}

__global__ void k_scanB() {
    __shared__ int s[SCAN_B];
    int v = (threadIdx.x < NBLK) ? g_bsum[threadIdx.x] : 0;
    s[threadIdx.x] = v;
    __syncthreads();
    for (int off = 1; off < SCAN_B; off <<= 1) {
        int t = (threadIdx.x >= off) ? s[threadIdx.x - off] : 0;
        __syncthreads();
        s[threadIdx.x] += t;
        __syncthreads();
    }
    g_bsum[threadIdx.x] = s[threadIdx.x] - v;  // exclusive
}

__global__ void k_scanC() {
    int i = blockIdx.x * blockDim.x + threadIdx.x;
    if (i < NN) {
        int rs = g_rowstart[i] + g_bsum[i / SCAN_B];
        g_rowstart[i] = rs;
        g_cursor[i]   = rs;
        int d = g_cnt[i];
        if (d < 1) d = 1;
        g_dn[i] = rsqrtf((float)d);
    }
}

__global__ void k_fill(const int* __restrict__ src, const int* __restrict__ dst) {
    int i = blockIdx.x * blockDim.x + threadIdx.x;
    if (i < NE) {
        int pos = atomicAdd(&g_cursor[dst[i]], 1);
        g_col[pos] = src[i];
    }
}

// ---------------- SpMM: out[i,:] = dn[i] * sum_{e in row i} dn[src]*x[src,:]
// warp per destination node, lanes cover 64 features as float2
__global__ void k_spmm(int in_sel, int out_sel) {
    int w = (blockIdx.x * blockDim.x + threadIdx.x) >> 5;
    int lane = threadIdx.x & 31;
    if (w >= NN) return;
    int s = g_rowstart[w];
    int d = g_cnt[w];
    const float2* x2 = (const float2*)FEAT(in_sel);
    float ax = 0.f, ay = 0.f;
    for (int e = 0; e < d; e++) {
        int srcn = __ldg(&g_col[s + e]);
        float wn = __ldg(&g_dn[srcn]);
        float2 v = __ldg(&x2[srcn * 32 + lane]);
        ax = fmaf(wn, v.x, ax);
        ay = fmaf(wn, v.y, ay);
    }
    float wd = g_dn[w];
    ((float2*)FEAT(out_sel))[w * 32 + lane] = make_float2(ax * wd, ay * wd);
}

// ---------------- GEMM: out = relu([f0|f1|f2|f3] @ W + b), W:[256,64] -------
// 64x64 output tile per block, 256 threads, 4x4 register tiles
__global__ void __launch_bounds__(256) k_gemm(
    int s0, int s1, int s2, int s3, int so,
    const float* __restrict__ W, const float* __restrict__ b)
{
    __shared__ float As[64 * 36];   // 64 rows x 32 k (pad to 36)
    __shared__ float Ws[32 * 64];   // 32 k x 64 cols
    int sel[4] = {s0, s1, s2, s3};
    int tid = threadIdx.x;
    int tx = tid & 15, ty = tid >> 4;
    int rbase = blockIdx.x * 64;
    float acc[4][4] = {};

    for (int kc = 0; kc < 8; kc++) {
        const float* fp = FEAT(sel[kc >> 1]);
        int c0 = (kc & 1) * 32;
        // stage A chunk [64 rows x 32 cols]
        #pragma unroll
        for (int i = 0; i < 2; i++) {
            int idx = tid + 256 * i;     // 0..511 float4 slots
            int r = idx >> 3, c4 = idx & 7;
            int row = rbase + r;
            float4 v = make_float4(0.f, 0.f, 0.f, 0.f);
            if (row < NN) v = *(const float4*)&fp[row * 64 + c0 + c4 * 4];
            *(float4*)&As[r * 36 + c4 * 4] = v;
        }
        // stage W chunk [32 x 64]
        #pragma unroll
        for (int i = 0; i < 2; i++) {
            int idx = tid + 256 * i;     // 0..511 float4 slots
            *(float4*)&Ws[idx * 4] = *(const float4*)&W[kc * 2048 + idx * 4];
        }
        __syncthreads();
        #pragma unroll
        for (int k = 0; k < 32; k += 4) {
            float4 a[4], w[4];
            #pragma unroll
            for (int rr = 0; rr < 4; rr++)
                a[rr] = *(float4*)&As[(ty * 4 + rr) * 36 + k];
            #pragma unroll
            for (int kk = 0; kk < 4; kk++)
                w[kk] = *(float4*)&Ws[(k + kk) * 64 + tx * 4];
            #pragma unroll
            for (int kk = 0; kk < 4; kk++) {
                #pragma unroll
                for (int rr = 0; rr < 4; rr++) {
                    float av = (kk == 0) ? a[rr].x : (kk == 1) ? a[rr].y
                             : (kk == 2) ? a[rr].z : a[rr].w;
                    acc[rr][0] = fmaf(av, w[kk].x, acc[rr][0]);
                    acc[rr][1] = fmaf(av, w[kk].y, acc[rr][1]);
                    acc[rr][2] = fmaf(av, w[kk].z, acc[rr][2]);
                    acc[rr][3] = fmaf(av, w[kk].w, acc[rr][3]);
                }
            }
        }
        __syncthreads();
    }
    float* outp = FEAT(so);
    float4 bias = *(const float4*)&b[tx * 4];
    #pragma unroll
    for (int rr = 0; rr < 4; rr++) {
        int row = rbase + ty * 4 + rr;
        if (row < NN) {
            float4 o;
            o.x = fmaxf(acc[rr][0] + bias.x, 0.f);
            o.y = fmaxf(acc[rr][1] + bias.y, 0.f);
            o.z = fmaxf(acc[rr][2] + bias.z, 0.f);
            o.w = fmaxf(acc[rr][3] + bias.w, 0.f);
            *(float4*)&outp[row * 64 + tx * 4] = o;
        }
    }
}

// ---------------- readout: per-graph sum + count (graph_ids sorted) ---------
// warp per 128-node chunk; register-accumulate runs, flush on graph change
__global__ void k_readout(int in_sel, const int* __restrict__ gids) {
    int w = (blockIdx.x * blockDim.x + threadIdx.x) >> 5;
    int lane = threadIdx.x & 31;
    int n0 = w * 128;
    if (n0 >= NN) return;
    int n1 = n0 + 128;
    if (n1 > NN) n1 = NN;
    const float2* x2 = (const float2*)FEAT(in_sel);
    float ax = 0.f, ay = 0.f;
    int run = 0;
    int cur = __ldg(&gids[n0]);
    for (int n = n0; n < n1; n++) {
        int g = __ldg(&gids[n]);
        if (g != cur) {
            atomicAdd(&g_gsum[cur * 64 + lane * 2],     ax);
            atomicAdd(&g_gsum[cur * 64 + lane * 2 + 1], ay);
            if (lane == 0) atomicAdd(&g_gcnt[cur], run);
            ax = 0.f; ay = 0.f; run = 0; cur = g;
        }
        float2 v = __ldg(&x2[n * 32 + lane]);
        ax += v.x; ay += v.y; run++;
    }
    atomicAdd(&g_gsum[cur * 64 + lane * 2],     ax);
    atomicAdd(&g_gsum[cur * 64 + lane * 2 + 1], ay);
    if (lane == 0) atomicAdd(&g_gcnt[cur], run);
}

// ---------------- final: mean -> @embW + embb -> L2 normalize ---------------
__global__ void k_final(const float* __restrict__ embW, const float* __restrict__ embb,
                        float* __restrict__ out) {
    __shared__ float hg[64];
    __shared__ float red[128];
    int g = blockIdx.x, tid = threadIdx.x;
    if (tid < 64) {
        float c = (float)g_gcnt[g];
        if (c < 1.f) c = 1.f;
        hg[tid] = g_gsum[g * 64 + tid] / c;
    }
    __syncthreads();
    float o = embb[tid];
    #pragma unroll
    for (int d = 0; d < 64; d++)
        o = fmaf(hg[d], __ldg(&embW[d * 128 + tid]), o);
    red[tid] = o * o;
    __syncthreads();
    for (int s = 64; s > 0; s >>= 1) {
        if (tid < s) red[tid] += red[tid + s];
        __syncthreads();
    }
    float nrm = sqrtf(red[0]);
    if (nrm < 1e-12f) nrm = 1e-12f;
    out[g * 128 + tid] = o / nrm;
}

// ---------------- launch ----------------------------------------------------
extern "C" void kernel_launch(void* const* d_in, const int* in_sizes, int n_in,
                              void* d_out, int out_size) {
    const float* h    = (const float*)d_in[0];
    const int*   src  = (const int*)d_in[1];
    const int*   dst  = (const int*)d_in[2];
    const int*   gids = (const int*)d_in[3];
    const float* W0   = (const float*)d_in[4];
    const float* b0   = (const float*)d_in[5];
    const float* W1   = (const float*)d_in[6];
    const float* b1   = (const float*)d_in[7];
    const float* W2   = (const float*)d_in[8];
    const float* b2   = (const float*)d_in[9];
    const float* embW = (const float*)d_in[10];
    const float* embb = (const float*)d_in[11];
    float* out = (float*)d_out;

    // stage input into slot 0 (device-global addressing only; no host API)
    k_copyin<<<(FEAT_SZ / 4 + 255) / 256, 256>>>(h);

    // graph preprocessing (per-launch, deterministic work)
    k_zero<<<(NN + 255) / 256, 256>>>();
    k_count<<<(NE + 255) / 256, 256>>>(dst);
    k_scanA<<<NBLK, SCAN_B>>>();
    k_scanB<<<1, SCAN_B>>>();
    k_scanC<<<(NN + 255) / 256, 256>>>();
    k_fill<<<(NE + 255) / 256, 256>>>(src, dst);

    const float* Ws[3] = {W0, W1, W2};
    const float* bs[3] = {b0, b1, b2};
    const int spmm_blocks = (NN * 32 + 255) / 256;   // warp per node
    const int gemm_blocks = (NN + 63) / 64;

    int s_in = 0;
    int s_out = 4;
    for (int l = 0; l < 3; l++) {
        k_spmm<<<spmm_blocks, 256>>>(s_in, 1);
        k_spmm<<<spmm_blocks, 256>>>(1, 2);
        k_spmm<<<spmm_blocks, 256>>>(2, 3);
        k_gemm<<<gemm_blocks, 256>>>(s_in, 1, 2, 3, s_out, Ws[l], bs[l]);
        s_in = s_out;
        s_out = (s_out == 4) ? 5 : 4;
    }
    // s_in now holds the last layer's output

    const int ro_warps = (NN + 127) / 128;
    k_readout<<<(ro_warps * 32 + 255) / 256, 256>>>(s_in, gids);
    k_final<<<NGR, 128>>>(embW, embb, out);
}

// round 3
// speedup vs baseline: 1.0773x; 1.0773x over previous
#include <cuda_runtime.h>

#define NN 100000
#define NE 800000
#define HIDD 64
#define EMBD 128
#define NGR 64
#define SCAN_B 512
#define NBLK ((NN + SCAN_B - 1) / SCAN_B)   // 196
#define FEAT_SZ (NN * HIDD)

// ---------------- scratch (device globals; no allocation allowed) ----------
__device__ int   g_cnt[NN];          // in-degree
__device__ int   g_rowstart[NN];     // CSR row start (by dst)
__device__ int   g_cursor[NN];       // fill cursors
__device__ int   g_col[NE];          // src node per incoming edge
__device__ float g_w[NE];            // per-edge weight dn[src]*dn[dst]
__device__ float g_dn[NN];           // deg^-1/2 (clamped)
__device__ int   g_bsum[SCAN_B];     // scan partials
// feature slots: 0 = layer input, 1..3 = hop buffers, 4/5 = layer out ping-pong
__device__ float g_feat[6 * FEAT_SZ];
__device__ float g_gsum[NGR * HIDD];
__device__ int   g_gcnt[NGR];

__device__ __forceinline__ float* FEAT(int s) { return g_feat + (size_t)s * FEAT_SZ; }

// ---------------- copy input h into slot 0 ----------------------------------
__global__ void k_copyin(const float* __restrict__ h) {
    int i = blockIdx.x * blockDim.x + threadIdx.x;   // float4 index
    if (i < FEAT_SZ / 4)
        ((float4*)g_feat)[i] = ((const float4*)h)[i];
}

// ---------------- graph preprocessing --------------------------------------
__global__ void k_zero() {
    int i = blockIdx.x * blockDim.x + threadIdx.x;
    if (i < NN) g_cnt[i] = 0;
    if (i < NGR * HIDD) g_gsum[i] = 0.f;
    if (i < NGR) g_gcnt[i] = 0;
}

__global__ void k_count(const int* __restrict__ dst) {
    int i = blockIdx.x * blockDim.x + threadIdx.x;
    if (i < NE) atomicAdd(&g_cnt[dst[i]], 1);
}

__global__ void k_scanA() {
    __shared__ int s[SCAN_B];
    int i = blockIdx.x * SCAN_B + threadIdx.x;
    int v = (i < NN) ? g_cnt[i] : 0;
    s[threadIdx.x] = v;
    __syncthreads();
    for (int off = 1; off < SCAN_B; off <<= 1) {
        int t = (threadIdx.x >= off) ? s[threadIdx.x - off] : 0;
        __syncthreads();
        s[threadIdx.x] += t;
        __syncthreads();
    }
    if (i < NN) g_rowstart[i] = s[threadIdx.x] - v;  // exclusive within block
    if (threadIdx.x == SCAN_B - 1) g_bsum[blockIdx.x] = s[SCAN_B - 1];
}

__global__ void k_scanB() {
    __shared__ int s[SCAN_B];
    int v = (threadIdx.x < NBLK) ? g_bsum[threadIdx.x] : 0;
    s[threadIdx.x] = v;
    __syncthreads();
    for (int off = 1; off < SCAN_B; off <<= 1) {
        int t = (threadIdx.x >= off) ? s[threadIdx.x - off] : 0;
        __syncthreads();
        s[threadIdx.x] += t;
        __syncthreads();
    }
    g_bsum[threadIdx.x] = s[threadIdx.x] - v;  // exclusive
}

__global__ void k_scanC() {
    int i = blockIdx.x * blockDim.x + threadIdx.x;
    if (i < NN) {
        int rs = g_rowstart[i] + g_bsum[i / SCAN_B];
        g_rowstart[i] = rs;
        g_cursor[i]   = rs;
        int d = g_cnt[i];
        if (d < 1) d = 1;
        g_dn[i] = rsqrtf((float)d);
    }
}

__global__ void k_fill(const int* __restrict__ src, const int* __restrict__ dst) {
    int i = blockIdx.x * blockDim.x + threadIdx.x;
    if (i < NE) {
        int s = src[i], d = dst[i];
        int pos = atomicAdd(&g_cursor[d], 1);
        g_col[pos] = s;
        g_w[pos] = __ldg(&g_dn[s]) * __ldg(&g_dn[d]);
    }
}

// ---------------- SpMM: out[i,:] = sum_{e in row i} w_e * x[src_e,:] --------
// warp per destination row; half-warps process edges e, e+1; lanes hold float4
__global__ void __launch_bounds__(256) k_spmm(int in_sel, int out_sel) {
    int w = (blockIdx.x * blockDim.x + threadIdx.x) >> 5;
    int lane = threadIdx.x & 31;
    if (w >= NN) return;
    int s = g_rowstart[w];
    int d = g_cnt[w];
    int half = lane >> 4;          // 0 or 1
    int hl = lane & 15;            // lane within half-warp
    const float4* __restrict__ x4 = (const float4*)FEAT(in_sel);
    float4 acc = make_float4(0.f, 0.f, 0.f, 0.f);
    int e = 0;
    #pragma unroll 2
    for (; e + 2 <= d; e += 2) {
        int idx = s + e + half;
        int srcn = __ldg(&g_col[idx]);
        float we = __ldg(&g_w[idx]);
        float4 v = __ldg(&x4[srcn * 16 + hl]);
        acc.x = fmaf(we, v.x, acc.x);
        acc.y = fmaf(we, v.y, acc.y);
        acc.z = fmaf(we, v.z, acc.z);
        acc.w = fmaf(we, v.w, acc.w);
    }
    if (e < d && half == 0) {      // odd tail: half 0 only
        int idx = s + e;
        int srcn = __ldg(&g_col[idx]);
        float we = __ldg(&g_w[idx]);
        float4 v = __ldg(&x4[srcn * 16 + hl]);
        acc.x = fmaf(we, v.x, acc.x);
        acc.y = fmaf(we, v.y, acc.y);
        acc.z = fmaf(we, v.z, acc.z);
        acc.w = fmaf(we, v.w, acc.w);
    }
    // combine the two half-warp partials (same feature columns)
    acc.x += __shfl_xor_sync(0xffffffff, acc.x, 16);
    acc.y += __shfl_xor_sync(0xffffffff, acc.y, 16);
    acc.z += __shfl_xor_sync(0xffffffff, acc.z, 16);
    acc.w += __shfl_xor_sync(0xffffffff, acc.w, 16);
    if (half == 0)
        ((float4*)FEAT(out_sel))[w * 16 + hl] = acc;
}

// ---------------- GEMM: out = relu([f0|f1|f2|f3] @ W + b), W:[256,64] -------
// 64x64 output tile per block, 256 threads, 4x4 register tiles
__global__ void __launch_bounds__(256) k_gemm(
    int s0, int s1, int s2, int s3, int so,
    const float* __restrict__ W, const float* __restrict__ b)
{
    __shared__ float As[64 * 36];   // 64 rows x 32 k (pad to 36)
    __shared__ float Ws[32 * 64];   // 32 k x 64 cols
    int sel[4] = {s0, s1, s2, s3};
    int tid = threadIdx.x;
    int tx = tid & 15, ty = tid >> 4;
    int rbase = blockIdx.x * 64;
    float acc[4][4] = {};

    for (int kc = 0; kc < 8; kc++) {
        const float* fp = FEAT(sel[kc >> 1]);
        int c0 = (kc & 1) * 32;
        // stage A chunk [64 rows x 32 cols]
        #pragma unroll
        for (int i = 0; i < 2; i++) {
            int idx = tid + 256 * i;     // 0..511 float4 slots
            int r = idx >> 3, c4 = idx & 7;
            int row = rbase + r;
            float4 v = make_float4(0.f, 0.f, 0.f, 0.f);
            if (row < NN) v = *(const float4*)&fp[row * 64 + c0 + c4 * 4];
            *(float4*)&As[r * 36 + c4 * 4] = v;
        }
        // stage W chunk [32 x 64]
        #pragma unroll
        for (int i = 0; i < 2; i++) {
            int idx = tid + 256 * i;     // 0..511 float4 slots
            *(float4*)&Ws[idx * 4] = *(const float4*)&W[kc * 2048 + idx * 4];
        }
        __syncthreads();
        #pragma unroll
        for (int k = 0; k < 32; k += 4) {
            float4 a[4], w[4];
            #pragma unroll
            for (int rr = 0; rr < 4; rr++)
                a[rr] = *(float4*)&As[(ty * 4 + rr) * 36 + k];
            #pragma unroll
            for (int kk = 0; kk < 4; kk++)
                w[kk] = *(float4*)&Ws[(k + kk) * 64 + tx * 4];
            #pragma unroll
            for (int kk = 0; kk < 4; kk++) {
                #pragma unroll
                for (int rr = 0; rr < 4; rr++) {
                    float av = (kk == 0) ? a[rr].x : (kk == 1) ? a[rr].y
                             : (kk == 2) ? a[rr].z : a[rr].w;
                    acc[rr][0] = fmaf(av, w[kk].x, acc[rr][0]);
                    acc[rr][1] = fmaf(av, w[kk].y, acc[rr][1]);
                    acc[rr][2] = fmaf(av, w[kk].z, acc[rr][2]);
                    acc[rr][3] = fmaf(av, w[kk].w, acc[rr][3]);
                }
            }
        }
        __syncthreads();
    }
    float* outp = FEAT(so);
    float4 bias = *(const float4*)&b[tx * 4];
    #pragma unroll
    for (int rr = 0; rr < 4; rr++) {
        int row = rbase + ty * 4 + rr;
        if (row < NN) {
            float4 o;
            o.x = fmaxf(acc[rr][0] + bias.x, 0.f);
            o.y = fmaxf(acc[rr][1] + bias.y, 0.f);
            o.z = fmaxf(acc[rr][2] + bias.z, 0.f);
            o.w = fmaxf(acc[rr][3] + bias.w, 0.f);
            *(float4*)&outp[row * 64 + tx * 4] = o;
        }
    }
}

// ---------------- readout: per-graph sum + count (graph_ids sorted) ---------
// warp per 128-node chunk; register-accumulate runs, flush on graph change
__global__ void k_readout(int in_sel, const int* __restrict__ gids) {
    int w = (blockIdx.x * blockDim.x + threadIdx.x) >> 5;
    int lane = threadIdx.x & 31;
    int n0 = w * 128;
    if (n0 >= NN) return;
    int n1 = n0 + 128;
    if (n1 > NN) n1 = NN;
    const float2* x2 = (const float2*)FEAT(in_sel);
    float ax = 0.f, ay = 0.f;
    int run = 0;
    int cur = __ldg(&gids[n0]);
    for (int n = n0; n < n1; n++) {
        int g = __ldg(&gids[n]);
        if (g != cur) {
            atomicAdd(&g_gsum[cur * 64 + lane * 2],     ax);
            atomicAdd(&g_gsum[cur * 64 + lane * 2 + 1], ay);
            if (lane == 0) atomicAdd(&g_gcnt[cur], run);
            ax = 0.f; ay = 0.f; run = 0; cur = g;
        }
        float2 v = __ldg(&x2[n * 32 + lane]);
        ax += v.x; ay += v.y; run++;
    }
    atomicAdd(&g_gsum[cur * 64 + lane * 2],     ax);
    atomicAdd(&g_gsum[cur * 64 + lane * 2 + 1], ay);
    if (lane == 0) atomicAdd(&g_gcnt[cur], run);
}

// ---------------- final: mean -> @embW + embb -> L2 normalize ---------------
__global__ void k_final(const float* __restrict__ embW, const float* __restrict__ embb,
                        float* __restrict__ out) {
    __shared__ float hg[64];
    __shared__ float red[128];
    int g = blockIdx.x, tid = threadIdx.x;
    if (tid < 64) {
        float c = (float)g_gcnt[g];
        if (c < 1.f) c = 1.f;
        hg[tid] = g_gsum[g * 64 + tid] / c;
    }
    __syncthreads();
    float o = embb[tid];
    #pragma unroll
    for (int d = 0; d < 64; d++)
        o = fmaf(hg[d], __ldg(&embW[d * 128 + tid]), o);
    red[tid] = o * o;
    __syncthreads();
    for (int s = 64; s > 0; s >>= 1) {
        if (tid < s) red[tid] += red[tid + s];
        __syncthreads();
    }
    float nrm = sqrtf(red[0]);
    if (nrm < 1e-12f) nrm = 1e-12f;
    out[g * 128 + tid] = o / nrm;
}

// ---------------- launch ----------------------------------------------------
extern "C" void kernel_launch(void* const* d_in, const int* in_sizes, int n_in,
                              void* d_out, int out_size) {
    const float* h    = (const float*)d_in[0];
    const int*   src  = (const int*)d_in[1];
    const int*   dst  = (const int*)d_in[2];
    const int*   gids = (const int*)d_in[3];
    const float* W0   = (const float*)d_in[4];
    const float* b0   = (const float*)d_in[5];
    const float* W1   = (const float*)d_in[6];
    const float* b1   = (const float*)d_in[7];
    const float* W2   = (const float*)d_in[8];
    const float* b2   = (const float*)d_in[9];
    const float* embW = (const float*)d_in[10];
    const float* embb = (const float*)d_in[11];
    float* out = (float*)d_out;

    // stage input into slot 0 (device-global addressing only; no host API)
    k_copyin<<<(FEAT_SZ / 4 + 255) / 256, 256>>>(h);

    // graph preprocessing (per-launch, deterministic work)
    k_zero<<<(NN + 255) / 256, 256>>>();
    k_count<<<(NE + 255) / 256, 256>>>(dst);
    k_scanA<<<NBLK, SCAN_B>>>();
    k_scanB<<<1, SCAN_B>>>();
    k_scanC<<<(NN + 255) / 256, 256>>>();
    k_fill<<<(NE + 255) / 256, 256>>>(src, dst);

    const float* Ws[3] = {W0, W1, W2};
    const float* bs[3] = {b0, b1, b2};
    const int spmm_blocks = (NN * 32 + 255) / 256;   // warp per node
    const int gemm_blocks = (NN + 63) / 64;

    int s_in = 0;
    int s_out = 4;
    for (int l = 0; l < 3; l++) {
        k_spmm<<<spmm_blocks, 256>>>(s_in, 1);
        k_spmm<<<spmm_blocks, 256>>>(1, 2);
        k_spmm<<<spmm_blocks, 256>>>(2, 3);
        k_gemm<<<gemm_blocks, 256>>>(s_in, 1, 2, 3, s_out, Ws[l], bs[l]);
        s_in = s_out;
        s_out = (s_out == 4) ? 5 : 4;
    }
    // s_in now holds the last layer's output

    const int ro_warps = (NN + 127) / 128;
    k_readout<<<(ro_warps * 32 + 255) / 256, 256>>>(s_in, gids);
    k_final<<<NGR, 128>>>(embW, embb, out);
}

// round 6
// speedup vs baseline: 1.1814x; 1.0966x over previous
#include <cuda_runtime.h>
#include <cstdint>

#define NN 100000
#define NE 800000
#define HIDD 64
#define EMBD 128
#define NGR 64
#define SCAN_B 512
#define NBLK ((NN + SCAN_B - 1) / SCAN_B)   // 196
#define FEAT_SZ (NN * HIDD)

// ---------------- scratch (device globals; no allocation allowed) ----------
__device__ int   g_cnt[NN];          // in-degree
__device__ int   g_rowstart[NN];     // CSR row start (by dst)
__device__ int   g_cursor[NN];       // fill cursors
__device__ int   g_col[NE];          // src node per incoming edge
__device__ float g_w[NE];            // per-edge weight dn[src]*dn[dst]
__device__ float g_dn[NN];           // deg^-1/2 (clamped)
__device__ int   g_bsum[SCAN_B];     // scan partials
// feature slots: 0 = layer input, 1..3 = hop buffers, 4/5 = layer out ping-pong
__device__ float g_feat[6 * FEAT_SZ];
__device__ float g_gsum[NGR * HIDD];
__device__ int   g_gcnt[NGR];

__device__ __forceinline__ float* FEAT(int s) { return g_feat + (size_t)s * FEAT_SZ; }

__device__ __forceinline__ uint32_t f2tf32(float f) {
    uint32_t o;
    asm("cvt.rna.tf32.f32 %0, %1;" : "=r"(o) : "f"(f));
    return o;
}

__device__ __forceinline__ void mma_tf32(float4& c,
    uint32_t a0, uint32_t a1, uint32_t a2, uint32_t a3,
    uint32_t b0, uint32_t b1)
{
    asm volatile(
        "mma.sync.aligned.m16n8k8.row.col.f32.tf32.tf32.f32 "
        "{%0,%1,%2,%3}, {%4,%5,%6,%7}, {%8,%9}, {%0,%1,%2,%3};"
        : "+f"(c.x), "+f"(c.y), "+f"(c.z), "+f"(c.w)
        : "r"(a0), "r"(a1), "r"(a2), "r"(a3), "r"(b0), "r"(b1));
}

// ---------------- copy input h into slot 0 ----------------------------------
__global__ void k_copyin(const float* __restrict__ h) {
    int i = blockIdx.x * blockDim.x + threadIdx.x;   // float4 index
    if (i < FEAT_SZ / 4)
        ((float4*)g_feat)[i] = ((const float4*)h)[i];
}

// ---------------- graph preprocessing --------------------------------------
__global__ void k_zero() {
    int i = blockIdx.x * blockDim.x + threadIdx.x;
    if (i < NN) g_cnt[i] = 0;
    if (i < NGR * HIDD) g_gsum[i] = 0.f;
    if (i < NGR) g_gcnt[i] = 0;
}

__global__ void k_count(const int* __restrict__ dst) {
    int i = blockIdx.x * blockDim.x + threadIdx.x;
    if (i < NE) atomicAdd(&g_cnt[dst[i]], 1);
}

__global__ void k_scanA() {
    __shared__ int s[SCAN_B];
    int i = blockIdx.x * SCAN_B + threadIdx.x;
    int v = (i < NN) ? g_cnt[i] : 0;
    s[threadIdx.x] = v;
    __syncthreads();
    for (int off = 1; off < SCAN_B; off <<= 1) {
        int t = (threadIdx.x >= off) ? s[threadIdx.x - off] : 0;
        __syncthreads();
        s[threadIdx.x] += t;
        __syncthreads();
    }
    if (i < NN) g_rowstart[i] = s[threadIdx.x] - v;  // exclusive within block
    if (threadIdx.x == SCAN_B - 1) g_bsum[blockIdx.x] = s[SCAN_B - 1];
}

__global__ void k_scanB() {
    __shared__ int s[SCAN_B];
    int v = (threadIdx.x < NBLK) ? g_bsum[threadIdx.x] : 0;
    s[threadIdx.x] = v;
    __syncthreads();
    for (int off = 1; off < SCAN_B; off <<= 1) {
        int t = (threadIdx.x >= off) ? s[threadIdx.x - off] : 0;
        __syncthreads();
        s[threadIdx.x] += t;
        __syncthreads();
    }
    g_bsum[threadIdx.x] = s[threadIdx.x] - v;  // exclusive
}

__global__ void k_scanC() {
    int i = blockIdx.x * blockDim.x + threadIdx.x;
    if (i < NN) {
        int rs = g_rowstart[i] + g_bsum[i / SCAN_B];
        g_rowstart[i] = rs;
        g_cursor[i]   = rs;
        int d = g_cnt[i];
        if (d < 1) d = 1;
        g_dn[i] = rsqrtf((float)d);
    }
}

__global__ void k_fill(const int* __restrict__ src, const int* __restrict__ dst) {
    int i = blockIdx.x * blockDim.x + threadIdx.x;
    if (i < NE) {
        int s = src[i], d = dst[i];
        int pos = atomicAdd(&g_cursor[d], 1);
        g_col[pos] = s;
        g_w[pos] = __ldg(&g_dn[s]) * __ldg(&g_dn[d]);
    }
}

// ---------------- SpMM: out[i,:] = sum_{e in row i} w_e * x[src_e,:] --------
// warp per destination row; half-warps process edges e, e+1; lanes hold float4
__global__ void __launch_bounds__(256) k_spmm(int in_sel, int out_sel) {
    int w = (blockIdx.x * blockDim.x + threadIdx.x) >> 5;
    int lane = threadIdx.x & 31;
    if (w >= NN) return;
    int s = g_rowstart[w];
    int d = g_cnt[w];
    int half = lane >> 4;          // 0 or 1
    int hl = lane & 15;            // lane within half-warp
    const float4* __restrict__ x4 = (const float4*)FEAT(in_sel);
    float4 acc = make_float4(0.f, 0.f, 0.f, 0.f);
    int e = 0;
    #pragma unroll 2
    for (; e + 2 <= d; e += 2) {
        int idx = s + e + half;
        int srcn = __ldg(&g_col[idx]);
        float we = __ldg(&g_w[idx]);
        float4 v = __ldg(&x4[srcn * 16 + hl]);
        acc.x = fmaf(we, v.x, acc.x);
        acc.y = fmaf(we, v.y, acc.y);
        acc.z = fmaf(we, v.z, acc.z);
        acc.w = fmaf(we, v.w, acc.w);
    }
    if (e < d && half == 0) {      // odd tail: half 0 only
        int idx = s + e;
        int srcn = __ldg(&g_col[idx]);
        float we = __ldg(&g_w[idx]);
        float4 v = __ldg(&x4[srcn * 16 + hl]);
        acc.x = fmaf(we, v.x, acc.x);
        acc.y = fmaf(we, v.y, acc.y);
        acc.z = fmaf(we, v.z, acc.z);
        acc.w = fmaf(we, v.w, acc.w);
    }
    // combine the two half-warp partials (same feature columns)
    acc.x += __shfl_xor_sync(0xffffffff, acc.x, 16);
    acc.y += __shfl_xor_sync(0xffffffff, acc.y, 16);
    acc.z += __shfl_xor_sync(0xffffffff, acc.z, 16);
    acc.w += __shfl_xor_sync(0xffffffff, acc.w, 16);
    if (half == 0)
        ((float4*)FEAT(out_sel))[w * 16 + hl] = acc;
}

// ---------------- GEMM: out = relu([f0|f1|f2|f3] @ W + b) via tf32 MMA ------
// block: 256 threads / 8 warps; tile M=256 x N=64; K=256 staged in 32-chunks
// warp w: m-tiles at rows {w*16, 128 + w*16}; 8 n-tiles of 8
#define AP 36   // As pitch (floats)
#define WP 72   // Ws pitch (floats)
__global__ void __launch_bounds__(256) k_gemm(
    int s0, int s1, int s2, int s3, int so,
    const float* __restrict__ W, const float* __restrict__ b)
{
    __shared__ float As[256 * AP];  // 36 KB, tf32-bit payload
    __shared__ float Ws[32 * WP];   //  9 KB, tf32-bit payload
    int sel[4] = {s0, s1, s2, s3};
    int tid = threadIdx.x;
    int wid = tid >> 5, lane = tid & 31;
    int g = lane >> 2, t = lane & 3;
    int rbase = blockIdx.x * 256;
    float4 acc[2][8];
    #pragma unroll
    for (int mt = 0; mt < 2; mt++)
        #pragma unroll
        for (int nt = 0; nt < 8; nt++)
            acc[mt][nt] = make_float4(0.f, 0.f, 0.f, 0.f);

    for (int kc = 0; kc < 8; kc++) {
        const float* fp = FEAT(sel[kc >> 1]);
        int c0 = (kc & 1) * 32;
        // stage A chunk [256 rows x 32 k], convert to tf32 bits
        #pragma unroll
        for (int i = 0; i < 8; i++) {
            int idx = tid + 256 * i;       // 0..2047 float4 slots
            int r = idx >> 3, c4 = idx & 7;
            int row = rbase + r;
            float4 v = make_float4(0.f, 0.f, 0.f, 0.f);
            if (row < NN) v = *(const float4*)&fp[row * 64 + c0 + c4 * 4];
            float* dstp = &As[r * AP + c4 * 4];
            dstp[0] = __uint_as_float(f2tf32(v.x));
            dstp[1] = __uint_as_float(f2tf32(v.y));
            dstp[2] = __uint_as_float(f2tf32(v.z));
            dstp[3] = __uint_as_float(f2tf32(v.w));
        }
        // stage W chunk [32 k x 64 n], convert to tf32 bits
        #pragma unroll
        for (int i = 0; i < 2; i++) {
            int idx = tid + 256 * i;       // 0..511 float4 slots (16 per row)
            int r = idx >> 4, c4 = idx & 15;
            float4 v = *(const float4*)&W[kc * 2048 + r * 64 + c4 * 4];
            float* dstp = &Ws[r * WP + c4 * 4];
            dstp[0] = __uint_as_float(f2tf32(v.x));
            dstp[1] = __uint_as_float(f2tf32(v.y));
            dstp[2] = __uint_as_float(f2tf32(v.z));
            dstp[3] = __uint_as_float(f2tf32(v.w));
        }
        __syncthreads();
        #pragma unroll
        for (int ks = 0; ks < 4; ks++) {
            int k0 = ks * 8;
            uint32_t bf0[8], bf1[8];
            #pragma unroll
            for (int nt = 0; nt < 8; nt++) {
                bf0[nt] = __float_as_uint(Ws[(k0 + t) * WP + nt * 8 + g]);
                bf1[nt] = __float_as_uint(Ws[(k0 + t + 4) * WP + nt * 8 + g]);
            }
            #pragma unroll
            for (int mt = 0; mt < 2; mt++) {
                int ro = mt * 128 + wid * 16;
                uint32_t a0 = __float_as_uint(As[(ro + g) * AP + k0 + t]);
                uint32_t a1 = __float_as_uint(As[(ro + g + 8) * AP + k0 + t]);
                uint32_t a2 = __float_as_uint(As[(ro + g) * AP + k0 + t + 4]);
                uint32_t a3 = __float_as_uint(As[(ro + g + 8) * AP + k0 + t + 4]);
                #pragma unroll
                for (int nt = 0; nt < 8; nt++)
                    mma_tf32(acc[mt][nt], a0, a1, a2, a3, bf0[nt], bf1[nt]);
            }
        }
        __syncthreads();
    }
    // epilogue: bias + relu, D fragment layout (g,2t)/(g+8,2t)
    float* outp = FEAT(so);
    #pragma unroll
    for (int mt = 0; mt < 2; mt++) {
        int r0 = rbase + mt * 128 + wid * 16 + g;
        int r1 = r0 + 8;
        #pragma unroll
        for (int nt = 0; nt < 8; nt++) {
            int col = nt * 8 + 2 * t;
            float bb0 = __ldg(&b[col]);
            float bb1 = __ldg(&b[col + 1]);
            float4 c = acc[mt][nt];
            if (r0 < NN) {
                float2 o = make_float2(fmaxf(c.x + bb0, 0.f), fmaxf(c.y + bb1, 0.f));
                *(float2*)&outp[r0 * 64 + col] = o;
            }
            if (r1 < NN) {
                float2 o = make_float2(fmaxf(c.z + bb0, 0.f), fmaxf(c.w + bb1, 0.f));
                *(float2*)&outp[r1 * 64 + col] = o;
            }
        }
    }
}

// ---------------- readout: per-graph sum + count (graph_ids sorted) ---------
__global__ void k_readout(int in_sel, const int* __restrict__ gids) {
    int w = (blockIdx.x * blockDim.x + threadIdx.x) >> 5;
    int lane = threadIdx.x & 31;
    int n0 = w * 128;
    if (n0 >= NN) return;
    int n1 = n0 + 128;
    if (n1 > NN) n1 = NN;
    const float2* x2 = (const float2*)FEAT(in_sel);
    float ax = 0.f, ay = 0.f;
    int run = 0;
    int cur = __ldg(&gids[n0]);
    for (int n = n0; n < n1; n++) {
        int g = __ldg(&gids[n]);
        if (g != cur) {
            atomicAdd(&g_gsum[cur * 64 + lane * 2],     ax);
            atomicAdd(&g_gsum[cur * 64 + lane * 2 + 1], ay);
            if (lane == 0) atomicAdd(&g_gcnt[cur], run);
            ax = 0.f; ay = 0.f; run = 0; cur = g;
        }
        float2 v = __ldg(&x2[n * 32 + lane]);
        ax += v.x; ay += v.y; run++;
    }
    atomicAdd(&g_gsum[cur * 64 + lane * 2],     ax);
    atomicAdd(&g_gsum[cur * 64 + lane * 2 + 1], ay);
    if (lane == 0) atomicAdd(&g_gcnt[cur], run);
}

// ---------------- final: mean -> @embW + embb -> L2 normalize ---------------
__global__ void k_final(const float* __restrict__ embW, const float* __restrict__ embb,
                        float* __restrict__ out) {
    __shared__ float hg[64];
    __shared__ float red[128];
    int g = blockIdx.x, tid = threadIdx.x;
    if (tid < 64) {
        float c = (float)g_gcnt[g];
        if (c < 1.f) c = 1.f;
        hg[tid] = g_gsum[g * 64 + tid] / c;
    }
    __syncthreads();
    float o = embb[tid];
    #pragma unroll
    for (int d = 0; d < 64; d++)
        o = fmaf(hg[d], __ldg(&embW[d * 128 + tid]), o);
    red[tid] = o * o;
    __syncthreads();
    for (int s = 64; s > 0; s >>= 1) {
        if (tid < s) red[tid] += red[tid + s];
        __syncthreads();
    }
    float nrm = sqrtf(red[0]);
    if (nrm < 1e-12f) nrm = 1e-12f;
    out[g * 128 + tid] = o / nrm;
}

// ---------------- launch ----------------------------------------------------
extern "C" void kernel_launch(void* const* d_in, const int* in_sizes, int n_in,
                              void* d_out, int out_size) {
    const float* h    = (const float*)d_in[0];
    const int*   src  = (const int*)d_in[1];
    const int*   dst  = (const int*)d_in[2];
    const int*   gids = (const int*)d_in[3];
    const float* W0   = (const float*)d_in[4];
    const float* b0   = (const float*)d_in[5];
    const float* W1   = (const float*)d_in[6];
    const float* b1   = (const float*)d_in[7];
    const float* W2   = (const float*)d_in[8];
    const float* b2   = (const float*)d_in[9];
    const float* embW = (const float*)d_in[10];
    const float* embb = (const float*)d_in[11];
    float* out = (float*)d_out;

    // stage input into slot 0 (device-global addressing only; no host API)
    k_copyin<<<(FEAT_SZ / 4 + 255) / 256, 256>>>(h);

    // graph preprocessing (per-launch, deterministic work)
    k_zero<<<(NN + 255) / 256, 256>>>();
    k_count<<<(NE + 255) / 256, 256>>>(dst);
    k_scanA<<<NBLK, SCAN_B>>>();
    k_scanB<<<1, SCAN_B>>>();
    k_scanC<<<(NN + 255) / 256, 256>>>();
    k_fill<<<(NE + 255) / 256, 256>>>(src, dst);

    const float* Ws[3] = {W0, W1, W2};
    const float* bs[3] = {b0, b1, b2};
    const int spmm_blocks = (NN * 32 + 255) / 256;   // warp per node
    const int gemm_blocks = (NN + 255) / 256;        // 256-row tiles

    int s_in = 0;
    int s_out = 4;
    for (int l = 0; l < 3; l++) {
        k_spmm<<<spmm_blocks, 256>>>(s_in, 1);
        k_spmm<<<spmm_blocks, 256>>>(1, 2);
        k_spmm<<<spmm_blocks, 256>>>(2, 3);
        k_gemm<<<gemm_blocks, 256>>>(s_in, 1, 2, 3, s_out, Ws[l], bs[l]);
        s_in = s_out;
        s_out = (s_out == 4) ? 5 : 4;
    }
    // s_in now holds the last layer's output

    const int ro_warps = (NN + 127) / 128;
    k_readout<<<(ro_warps * 32 + 255) / 256, 256>>>(s_in, gids);
    k_final<<<NGR, 128>>>(embW, embb, out);
}